// round 1
// baseline (speedup 1.0000x reference)
#include <cuda_runtime.h>
#include <cuda_bf16.h>
#include <cstdint>

// Backlash scan: B=4096 sequences, T=2048 steps.
//   f1 = h((m_lo*x + m_lo*c_lo - prev)/m_lo),  f2 = h((prev - m_up*x - m_up*c_up)/m_up)
//   h(s) = (s>0) ? 0 : 1
//   out  = m_lo*x*f1 + m_lo*c_lo*f1 + m_up*x*f2 + m_up*c_up*f2 + prev*(1-f1)*(1-f2)
//
// Strategy: speculative chunked scan (C=16 chunks of L=128, warm-up W=32 from a
// guessed state) + bitwise validation + selective serial replay. Exact result.

#define BB 4096
#define TT 2048
#define CHUNKS 16
#define LCH (TT / CHUNKS)   // 128
#define WARM 32

__device__ float g_G[BB * CHUNKS];   // state entering chunk c (derived via warm-up)
__device__ float g_E[BB * CHUNKS];   // state leaving chunk c

// One backlash step. Replicates the reference's fp32 arithmetic with plain
// (non-FMA) IEEE ops; thresholds via sign tests (exact for nonzero m, which
// holds a.s. for Gaussian inputs).
__device__ __forceinline__ float bl_step(float prev, float xt, float4 w) {
    float m_lo = w.x, m_up = w.y, c_lo = w.z, c_up = w.w;
    float a  = __fmul_rn(m_lo, xt);    // m_lo * x
    float bq = __fmul_rn(m_lo, c_lo);  // m_lo * c_lo
    float cc = __fmul_rn(m_up, xt);    // m_up * x
    float d  = __fmul_rn(m_up, c_up);  // m_up * c_up
    // A1 = (m_lo*x + m_lo*c_lo) - prev ; A2 = (prev - m_up*x) - m_up*c_up
    float A1 = __fsub_rn(__fadd_rn(a, bq), prev);
    float A2 = __fsub_rn(__fsub_rn(prev, cc), d);
    // p = (A/m > 0)  <=>  f == 0
    bool p1 = ((A1 > 0.0f) && (m_lo > 0.0f)) || ((A1 < 0.0f) && (m_lo < 0.0f));
    bool p2 = ((A2 > 0.0f) && (m_up > 0.0f)) || ((A2 < 0.0f) && (m_up < 0.0f));
    float t1 = p1 ? 0.0f : a;
    float t2 = p1 ? 0.0f : bq;
    float t3 = p2 ? 0.0f : cc;
    float t4 = p2 ? 0.0f : d;
    float t5 = (p1 && p2) ? prev : 0.0f;
    // Left-associated 5-term sum, matching the reference expression order.
    return __fadd_rn(__fadd_rn(__fadd_rn(__fadd_rn(t1, t2), t3), t4), t5);
}

__global__ __launch_bounds__(128)
void backlash_phaseA(const float* __restrict__ x,
                     const float* __restrict__ w,
                     const float* __restrict__ out_prev,
                     float* __restrict__ out) {
    int tid = blockIdx.x * blockDim.x + threadIdx.x;   // 0 .. B*CHUNKS-1
    int b = tid / CHUNKS;
    int c = tid % CHUNKS;

    const float*  xb = x + (size_t)b * TT;
    const float4* wb = (const float4*)(w + (size_t)b * TT * 4);
    float*        ob = out + (size_t)b * TT;

    int t0 = c * LCH;
    float prev = (c == 0) ? out_prev[b] : 0.0f;
    int tw = (c == 0) ? t0 : (t0 - WARM);

    // Warm-up (speculative; merges with the true trajectory w.h.p.)
    for (int t = tw; t < t0; t += 4) {
        float4 xv = *(const float4*)(xb + t);
        float4 w0 = wb[t + 0];
        float4 w1 = wb[t + 1];
        float4 w2 = wb[t + 2];
        float4 w3 = wb[t + 3];
        prev = bl_step(prev, xv.x, w0);
        prev = bl_step(prev, xv.y, w1);
        prev = bl_step(prev, xv.z, w2);
        prev = bl_step(prev, xv.w, w3);
    }
    g_G[tid] = prev;

    // Main chunk: emit outputs.
    #pragma unroll 2
    for (int t = t0; t < t0 + LCH; t += 4) {
        float4 xv = *(const float4*)(xb + t);
        float4 w0 = wb[t + 0];
        float4 w1 = wb[t + 1];
        float4 w2 = wb[t + 2];
        float4 w3 = wb[t + 3];
        float4 o;
        prev = bl_step(prev, xv.x, w0); o.x = prev;
        prev = bl_step(prev, xv.y, w1); o.y = prev;
        prev = bl_step(prev, xv.z, w2); o.z = prev;
        prev = bl_step(prev, xv.w, w3); o.w = prev;
        *(float4*)(ob + t) = o;
    }
    g_E[tid] = prev;
}

// Validate chunk boundaries; serially replay any chunk whose speculative
// warm-up failed to merge (expected: none on this data, but exactness is
// guaranteed either way).
__global__ __launch_bounds__(128)
void backlash_phaseB(const float* __restrict__ x,
                     const float* __restrict__ w,
                     float* __restrict__ out) {
    int b = blockIdx.x * blockDim.x + threadIdx.x;   // 0 .. B-1
    if (b >= BB) return;

    float s = g_E[b * CHUNKS + 0];
    for (int c = 1; c < CHUNKS; c++) {
        float g = g_G[b * CHUNKS + c];
        if (s == g) {
            s = g_E[b * CHUNKS + c];
        } else {
            // Replay chunk c from the true incoming state.
            const float*  xb = x + (size_t)b * TT;
            const float4* wb = (const float4*)(w + (size_t)b * TT * 4);
            float*        ob = out + (size_t)b * TT;
            int t0 = c * LCH;
            for (int t = t0; t < t0 + LCH; t++) {
                s = bl_step(s, xb[t], wb[t]);
                ob[t] = s;
            }
        }
    }
}

extern "C" void kernel_launch(void* const* d_in, const int* in_sizes, int n_in,
                              void* d_out, int out_size) {
    const float* x = nullptr;        // (B, T, 1)    -> B*T elements
    const float* out_prev = nullptr; // (B, 1, 1)    -> B elements
    const float* w = nullptr;        // (B, T, 4)    -> B*T*4 elements
    for (int i = 0; i < n_in; i++) {
        if (in_sizes[i] == BB * TT)          x = (const float*)d_in[i];
        else if (in_sizes[i] == BB)          out_prev = (const float*)d_in[i];
        else if (in_sizes[i] == BB * TT * 4) w = (const float*)d_in[i];
    }
    float* out = (float*)d_out;

    backlash_phaseA<<<(BB * CHUNKS) / 128, 128>>>(x, w, out_prev, out);
    backlash_phaseB<<<BB / 128, 128>>>(x, w, out);
}

// round 2
// speedup vs baseline: 1.5595x; 1.5595x over previous
#include <cuda_runtime.h>
#include <cuda_bf16.h>
#include <cstdint>

// Backlash scan, B=4096, T=2048. Exact speculative chunked scan:
//   phaseA: 16 chunks/sequence, 32-step speculative warm-up, smem-staged
//           coalesced I/O (fixes L1 wavefront blowup of scattered per-lane streams).
//   phaseB: validate chunk boundaries bitwise; serial replay of any chunk whose
//           warm-up failed to merge (expected none; exactness guaranteed anyway).

#define BB 4096
#define TT 2048
#define CHUNKS 16
#define LCH (TT / CHUNKS)   // 128
#define WARM 32
#define SS 16               // steps per stage
#define NSTAGES 10          // 2 warm + 8 emit
#define TPB 128
#define STRIDE 17           // pad stride (coprime with 32) for conflict-free smem

__device__ float g_G[BB * CHUNKS];   // state entering chunk c (via warm-up)
__device__ float g_E[BB * CHUNKS];   // state leaving chunk c

// One backlash step, bit-identical to the reference's fp32 expression.
// Thresholds via sign tests (exact for nonzero m).
__device__ __forceinline__ float bl_step(float prev, float xt, float4 wv) {
    float m_lo = wv.x, m_up = wv.y, c_lo = wv.z, c_up = wv.w;
    float a  = __fmul_rn(m_lo, xt);
    float bq = __fmul_rn(m_lo, c_lo);
    float cc = __fmul_rn(m_up, xt);
    float d  = __fmul_rn(m_up, c_up);
    float A1 = __fsub_rn(__fadd_rn(a, bq), prev);
    float A2 = __fsub_rn(__fsub_rn(prev, cc), d);
    bool p1 = ((A1 > 0.0f) && (m_lo > 0.0f)) || ((A1 < 0.0f) && (m_lo < 0.0f));
    bool p2 = ((A2 > 0.0f) && (m_up > 0.0f)) || ((A2 < 0.0f) && (m_up < 0.0f));
    float t1 = p1 ? 0.0f : a;
    float t2 = p1 ? 0.0f : bq;
    float t3 = p2 ? 0.0f : cc;
    float t4 = p2 ? 0.0f : d;
    float t5 = (p1 && p2) ? prev : 0.0f;
    return __fadd_rn(__fadd_rn(__fadd_rn(__fadd_rn(t1, t2), t3), t4), t5);
}

__device__ __forceinline__ void cp16(uint32_t dst, const void* src) {
    asm volatile("cp.async.cg.shared.global [%0], [%1], 16;" :: "r"(dst), "l"(src));
}
__device__ __forceinline__ void cp4(uint32_t dst, const void* src) {
    asm volatile("cp.async.ca.shared.global [%0], [%1], 4;" :: "r"(dst), "l"(src));
}

__global__ __launch_bounds__(TPB)
void backlash_phaseA(const float* __restrict__ x,
                     const float* __restrict__ w,
                     const float* __restrict__ out_prev,
                     float* __restrict__ out) {
    __shared__ float4 sW[TPB * STRIDE];   // 34816 B
    __shared__ float  sX[TPB * STRIDE];   //  8704 B

    const int tid   = threadIdx.x;
    const int b_blk = blockIdx.x * 8;        // 8 sequences per block
    const int my_c  = tid & 15;
    const int my_b  = b_blk + (tid >> 4);
    const int gid   = my_b * CHUNKS + my_c;

    const uint32_t sWa = (uint32_t)__cvta_generic_to_shared(sW);
    const uint32_t sXa = (uint32_t)__cvta_generic_to_shared(sX);

    const int cp_bl = tid >> 4;   // copy role: which stream group
    const int cp_j  = tid & 15;   // copy role: which step within stage

    float prev = 0.0f;

    for (int s = 0; s < NSTAGES; s++) {
        // ---- coalesced copy of stage s (w: 16B/step, x: 4B/step) ----
        #pragma unroll
        for (int it = 0; it < 16; it++) {
            int sidx  = it * 8 + cp_bl;                // block-local stream 0..127
            int sb    = b_blk + (sidx >> 4);
            int sc    = sidx & 15;
            int tbase = sc * LCH - WARM + s * SS;
            if (tbase < 0) tbase = 0;                  // c==0 warm clamp (discarded)
            size_t t = (size_t)sb * TT + tbase + cp_j;
            cp16(sWa + (uint32_t)(sidx * STRIDE + cp_j) * 16, (const float4*)w + t);
            cp4 (sXa + (uint32_t)(sidx * STRIDE + cp_j) * 4,  x + t);
        }
        asm volatile("cp.async.commit_group;");
        asm volatile("cp.async.wait_group 0;");
        __syncthreads();

        // ---- compute 16 steps from smem ----
        const bool emit = (s >= 2);
        if (emit || my_c > 0) {
            #pragma unroll
            for (int j = 0; j < SS; j++) {
                float4 wv = sW[tid * STRIDE + j];
                float  xv = sX[tid * STRIDE + j];
                prev = bl_step(prev, xv, wv);
                if (emit) sX[tid * STRIDE + j] = prev;   // outputs into dead x slots
            }
        }
        if (s == 1) {             // warm-up done
            if (my_c == 0) prev = out_prev[my_b];
            g_G[gid] = prev;
        }
        __syncthreads();

        // ---- coalesced float4 write of this stage's outputs ----
        if (emit) {
            #pragma unroll
            for (int it = 0; it < 4; it++) {
                int sidx = it * 32 + (tid >> 2);
                int sb   = b_blk + (sidx >> 4);
                int sc   = sidx & 15;
                int j4   = tid & 3;
                float4 v;
                v.x = sX[sidx * STRIDE + j4 * 4 + 0];
                v.y = sX[sidx * STRIDE + j4 * 4 + 1];
                v.z = sX[sidx * STRIDE + j4 * 4 + 2];
                v.w = sX[sidx * STRIDE + j4 * 4 + 3];
                ((float4*)out)[(size_t)sb * (TT / 4) + sc * (LCH / 4)
                               + (s - 2) * (SS / 4) + j4] = v;
            }
            __syncthreads();   // outputs consumed before next stage's copy
        }
    }
    g_E[gid] = prev;
}

__device__ __noinline__ float bl_replay(const float* xb, const float4* wb,
                                        float* ob, int t0, float st) {
    for (int t = t0; t < t0 + LCH; t++) {
        st = bl_step(st, xb[t], wb[t]);
        ob[t] = st;
    }
    return st;
}

__global__ __launch_bounds__(128)
void backlash_phaseB(const float* __restrict__ x,
                     const float* __restrict__ w,
                     float* __restrict__ out) {
    int b = blockIdx.x * blockDim.x + threadIdx.x;
    if (b >= BB) return;

    // One round-trip: load all boundary states as independent float4s.
    float Ev[16], Gv[16];
    const float4* e4 = (const float4*)(g_E + b * CHUNKS);
    const float4* g4 = (const float4*)(g_G + b * CHUNKS);
    #pragma unroll
    for (int q = 0; q < 4; q++) {
        *(float4*)&Ev[q * 4] = e4[q];
        *(float4*)&Gv[q * 4] = g4[q];
    }

    float st = Ev[0];
    #pragma unroll
    for (int c = 1; c < CHUNKS; c++) {
        if (st == Gv[c]) {
            st = Ev[c];
        } else {
            st = bl_replay(x + (size_t)b * TT,
                           (const float4*)(w) + (size_t)b * TT,
                           out + (size_t)b * TT, c * LCH, st);
        }
    }
}

extern "C" void kernel_launch(void* const* d_in, const int* in_sizes, int n_in,
                              void* d_out, int out_size) {
    const float* x = nullptr;        // (B, T, 1)
    const float* out_prev = nullptr; // (B, 1, 1)
    const float* w = nullptr;        // (B, T, 4)
    for (int i = 0; i < n_in; i++) {
        if (in_sizes[i] == BB * TT)          x = (const float*)d_in[i];
        else if (in_sizes[i] == BB)          out_prev = (const float*)d_in[i];
        else if (in_sizes[i] == BB * TT * 4) w = (const float*)d_in[i];
    }
    float* out = (float*)d_out;

    backlash_phaseA<<<BB / 8, TPB>>>(x, w, out_prev, out);
    backlash_phaseB<<<BB / 128, 128>>>(x, w, out);
}

// round 3
// speedup vs baseline: 1.6082x; 1.0312x over previous
#include <cuda_runtime.h>
#include <cuda_bf16.h>
#include <cstdint>

// Backlash scan, B=4096, T=2048. Single fused kernel:
//  - 16 chunks/sequence, 24-step speculative warm-up
//  - double-buffered cp.async smem pipeline (8 steps/stage, 19 stages)
//  - in-block chunk-boundary validation + serial replay backstop (exact result)

#define BB 4096
#define TT 2048
#define CHUNKS 16
#define LCH 128            // TT / CHUNKS
#define SS 8               // steps per stage
#define WARMS 3            // warm-up stages
#define WARM (WARMS * SS)  // 24
#define NST (WARMS + LCH / SS)  // 19
#define TPB 128
#define STR 11             // float4 stride per stream: slots 0-7 = w, 8-9 = x/out, 10 = pad

// One backlash step, bit-identical to the reference fp32 expression.
// h-thresholds via sign tests (exact for nonzero m).
__device__ __forceinline__ float bl_step(float prev, float xt, float4 wv) {
    float m_lo = wv.x, m_up = wv.y, c_lo = wv.z, c_up = wv.w;
    float a  = __fmul_rn(m_lo, xt);
    float bq = __fmul_rn(m_lo, c_lo);
    float cc = __fmul_rn(m_up, xt);
    float d  = __fmul_rn(m_up, c_up);
    float A1 = __fsub_rn(__fadd_rn(a, bq), prev);
    float A2 = __fsub_rn(__fsub_rn(prev, cc), d);
    bool p1 = ((A1 > 0.0f) && (m_lo > 0.0f)) || ((A1 < 0.0f) && (m_lo < 0.0f));
    bool p2 = ((A2 > 0.0f) && (m_up > 0.0f)) || ((A2 < 0.0f) && (m_up < 0.0f));
    float t1 = p1 ? 0.0f : a;
    float t2 = p1 ? 0.0f : bq;
    float t3 = p2 ? 0.0f : cc;
    float t4 = p2 ? 0.0f : d;
    float t5 = (p1 && p2) ? prev : 0.0f;
    return __fadd_rn(__fadd_rn(__fadd_rn(__fadd_rn(t1, t2), t3), t4), t5);
}

__device__ __forceinline__ void cp16(uint32_t dst, const float4* src) {
    asm volatile("cp.async.cg.shared.global [%0], [%1], 16;" :: "r"(dst), "l"(src));
}

// Issue the coalesced cp.async copies for stage s into buffer base `sb32`.
__device__ __forceinline__ void issue_stage(const float* __restrict__ x,
                                            const float* __restrict__ w,
                                            int b_blk, int s, uint32_t sb32, int tid) {
    // w: 128 streams x 8 steps of float4  (8 per thread)
    #pragma unroll
    for (int it = 0; it < 8; it++) {
        int sidx  = it * 16 + (tid >> 3);
        int j     = tid & 7;
        int sb    = b_blk + (sidx >> 4);
        int sc    = sidx & 15;
        int tbase = sc * LCH - WARM + s * SS;
        if (tbase < 0) tbase = 0;              // c==0 warm clamp (discarded)
        cp16(sb32 + (uint32_t)(sidx * STR + j) * 16,
             (const float4*)w + (size_t)sb * TT + tbase + j);
    }
    // x: 128 streams x 2 float4 (2 per thread); tbase is always 16B-aligned
    #pragma unroll
    for (int it = 0; it < 2; it++) {
        int sidx  = it * 64 + (tid >> 1);
        int k     = tid & 1;
        int sb    = b_blk + (sidx >> 4);
        int sc    = sidx & 15;
        int tbase = sc * LCH - WARM + s * SS;
        if (tbase < 0) tbase = 0;
        cp16(sb32 + (uint32_t)(sidx * STR + 8 + k) * 16,
             (const float4*)(x + (size_t)sb * TT + tbase) + k);
    }
    asm volatile("cp.async.commit_group;");
}

__global__ __launch_bounds__(TPB)
void backlash_fused(const float* __restrict__ x,
                    const float* __restrict__ w,
                    const float* __restrict__ out_prev,
                    float* __restrict__ out) {
    __shared__ float4 sB[2][TPB * STR];   // 45056 B
    __shared__ float  sG[TPB];            // state entering chunk (post warm-up)
    __shared__ float  sE[TPB];            // state leaving chunk

    const int tid   = threadIdx.x;
    const int b_blk = blockIdx.x * 8;     // 8 sequences per block
    const int my_c  = tid & 15;
    const int my_b  = b_blk + (tid >> 4);

    const uint32_t s0 = (uint32_t)__cvta_generic_to_shared(&sB[0][0]);
    const uint32_t s1 = (uint32_t)__cvta_generic_to_shared(&sB[1][0]);

    float prev = 0.0f;

    issue_stage(x, w, b_blk, 0, s0, tid);

    for (int s = 0; s < NST; s++) {
        const int buf = s & 1;
        if (s + 1 < NST)
            issue_stage(x, w, b_blk, s + 1, (s + 1) & 1 ? s1 : s0, tid);
        if (s + 1 < NST) { asm volatile("cp.async.wait_group 1;"); }
        else             { asm volatile("cp.async.wait_group 0;"); }
        __syncthreads();

        const bool emit = (s >= WARMS);
        if (emit || my_c > 0) {
            // x for my 8 steps (conflict-free LDS.128)
            float4 x0 = sB[buf][tid * STR + 8];
            float4 x1 = sB[buf][tid * STR + 9];
            float o[8];
            const float* xs = &x0.x;   // x0,x1 adjacent? not guaranteed; unroll manually
            float xv[8] = {x0.x, x0.y, x0.z, x0.w, x1.x, x1.y, x1.z, x1.w};
            #pragma unroll
            for (int j = 0; j < SS; j++) {
                float4 wv = sB[buf][tid * STR + j];
                prev = bl_step(prev, xv[j], wv);
                o[j] = prev;
            }
            if (emit) {
                // outputs back into the (consumed) x slots, conflict-free STS.128
                sB[buf][tid * STR + 8] = make_float4(o[0], o[1], o[2], o[3]);
                sB[buf][tid * STR + 9] = make_float4(o[4], o[5], o[6], o[7]);
            }
            (void)xs;
        }
        if (s == WARMS - 1) {           // warm-up complete
            if (my_c == 0) prev = out_prev[my_b];
            sG[tid] = prev;
        }
        __syncthreads();

        if (emit) {
            // coalesced float4 write of this stage's outputs
            #pragma unroll
            for (int it = 0; it < 2; it++) {
                int sidx = it * 64 + (tid >> 1);
                int k    = tid & 1;
                int sb   = b_blk + (sidx >> 4);
                int sc   = sidx & 15;
                float4 v = sB[buf][sidx * STR + 8 + k];
                ((float4*)out)[(size_t)sb * (TT / 4) + sc * (LCH / 4)
                               + (s - WARMS) * (SS / 4) + k] = v;
            }
            __syncthreads();   // outputs consumed before this buffer is refilled
        }
    }

    // ---- in-block validation + replay backstop (exactness guarantee) ----
    sE[tid] = prev;
    __syncthreads();

    if (tid < 8) {
        const int b = b_blk + tid;
        const float*  xb = x + (size_t)b * TT;
        const float4* wb = (const float4*)w + (size_t)b * TT;
        float*        ob = out + (size_t)b * TT;
        float st = sE[tid * 16];
        #pragma unroll 1
        for (int c = 1; c < CHUNKS; c++) {
            if (st == sG[tid * 16 + c]) {
                st = sE[tid * 16 + c];
            } else {
                // speculative warm-up failed to merge: serial replay of chunk c
                for (int t = c * LCH; t < (c + 1) * LCH; t++) {
                    st = bl_step(st, xb[t], wb[t]);
                    ob[t] = st;
                }
            }
        }
    }
}

extern "C" void kernel_launch(void* const* d_in, const int* in_sizes, int n_in,
                              void* d_out, int out_size) {
    const float* x = nullptr;        // (B, T, 1)
    const float* out_prev = nullptr; // (B, 1, 1)
    const float* w = nullptr;        // (B, T, 4)
    for (int i = 0; i < n_in; i++) {
        if (in_sizes[i] == BB * TT)          x = (const float*)d_in[i];
        else if (in_sizes[i] == BB)          out_prev = (const float*)d_in[i];
        else if (in_sizes[i] == BB * TT * 4) w = (const float*)d_in[i];
    }
    float* out = (float*)d_out;

    backlash_fused<<<BB / 8, TPB>>>(x, w, out_prev, out);
}